// round 8
// baseline (speedup 1.0000x reference)
#include <cuda_runtime.h>
#include <cstdint>
#include <math.h>

// Binary MLP B=16384, D=H=1024, C=10.
// L1,L3: bit-packed XOR + balanced CSA/POPC (q=16) with integer BN threshold.
// L2: bf16 legacy mma.sync GEMM (exact for +-1 with f32 accum) as a pipe test.

#define NB       16384
#define KW       32
#define HN       1024
#define ROWS_PB  128
#define GRP_PB   8
#define THREADS  256

// -------- device scratch (allocation-free rule) --------
__device__ unsigned        g_act[2][NB * KW];     // packed bit activations
__device__ unsigned        g_wt[2][KW * HN];      // W1, W3 packed (transposed)
__device__ unsigned short  g_abf[NB * HN];        // bf16 activations (L1 -> L2)
__device__ unsigned short  g_wbf[HN * HN];        // W2 as bf16 [n][k]
__device__ float2          g_thr2[HN];            // L2 thresholds (mul, thr)
__device__ unsigned        g_w4[10 * KW];         // packed W4

__device__ __forceinline__ uint32_t smem_u32(const void* p) {
    uint32_t a;
    asm("{ .reg .u64 t; cvta.to.shared.u64 t, %1; cvt.u32.u64 %0, t; }" : "=r"(a) : "l"(p));
    return a;
}
__device__ __forceinline__ unsigned lop3_96(unsigned a, unsigned b, unsigned c) { // a^b^c
    unsigned r;
    asm("lop3.b32 %0, %1, %2, %3, 0x96;" : "=r"(r) : "r"(a), "r"(b), "r"(c));
    return r;
}
__device__ __forceinline__ unsigned lop3_e8(unsigned a, unsigned b, unsigned c) { // maj
    unsigned r;
    asm("lop3.b32 %0, %1, %2, %3, 0xE8;" : "=r"(r) : "r"(a), "r"(b), "r"(c));
    return r;
}
#define FA(a, b, c, s, cy) { s = lop3_96(a, b, c); cy = lop3_e8(a, b, c); }

// ======================= prep kernels =======================
__global__ void pack_x_kernel(const float* __restrict__ x) {
    int t = blockIdx.x * blockDim.x + threadIdx.x;
    if (t >= NB * KW) return;
    int row = t >> 5, w = t & 31;
    const float4* p = reinterpret_cast<const float4*>(x + (size_t)row * 1024 + w * 32);
    unsigned bits = 0;
#pragma unroll
    for (int i = 0; i < 8; i++) {
        float4 v = p[i];
        bits |= ((2.0f * v.x - 1.0f) >= 0.0f ? 1u : 0u) << (4 * i + 0);
        bits |= ((2.0f * v.y - 1.0f) >= 0.0f ? 1u : 0u) << (4 * i + 1);
        bits |= ((2.0f * v.z - 1.0f) >= 0.0f ? 1u : 0u) << (4 * i + 2);
        bits |= ((2.0f * v.w - 1.0f) >= 0.0f ? 1u : 0u) << (4 * i + 3);
    }
    g_act[0][t] = bits;
}

__global__ void pack_w_kernel(const float* __restrict__ W, int widx) {
    int t = blockIdx.x * blockDim.x + threadIdx.x;
    if (t >= KW * HN) return;
    int n = t & (HN - 1), j = t >> 10;
    const float4* p = reinterpret_cast<const float4*>(W + (size_t)n * 1024 + j * 32);
    unsigned bits = 0;
#pragma unroll
    for (int i = 0; i < 8; i++) {
        float4 v = p[i];
        bits |= (v.x >= 0.0f ? 1u : 0u) << (4 * i + 0);
        bits |= (v.y >= 0.0f ? 1u : 0u) << (4 * i + 1);
        bits |= (v.z >= 0.0f ? 1u : 0u) << (4 * i + 2);
        bits |= (v.w >= 0.0f ? 1u : 0u) << (4 * i + 3);
    }
    g_wt[widx][j * HN + n] = bits;
}

__global__ void conv_w2(const float* __restrict__ W) {
    int t = blockIdx.x * blockDim.x + threadIdx.x;   // one per 4 elems
    if (t >= HN * HN / 4) return;
    float4 v = reinterpret_cast<const float4*>(W)[t];
    ushort4 o;
    o.x = (v.x >= 0.0f) ? 0x3F80 : 0xBF80;
    o.y = (v.y >= 0.0f) ? 0x3F80 : 0xBF80;
    o.z = (v.z >= 0.0f) ? 0x3F80 : 0xBF80;
    o.w = (v.w >= 0.0f) ? 0x3F80 : 0xBF80;
    reinterpret_cast<ushort4*>(g_wbf)[t] = o;
}

__global__ void thr2_kernel(const float* __restrict__ g, const float* __restrict__ b,
                            const float* __restrict__ m, const float* __restrict__ v) {
    int n = blockIdx.x * blockDim.x + threadIdx.x;
    if (n >= HN) return;
    double sc = (double)g[n] / sqrt((double)v[n] + 1e-5);
    float mf, tf;
    if (sc > 0.0) {
        double T = (1024.0 - (double)m[n] + (double)b[n] / sc) * 0.5;
        T = fmin(fmax(T, -2000.0), 2000.0);
        mf = 1.0f;  tf = (float)(1024.0 - 2.0 * floor(T));   // bit <=> s >= A
    } else if (sc < 0.0) {
        double T = (1024.0 - (double)m[n] + (double)b[n] / sc) * 0.5;
        T = fmin(fmax(T, -2000.0), 2000.0);
        mf = -1.0f; tf = -(float)(1024.0 - 2.0 * ceil(T));   // bit <=> -s >= -B
    } else {
        mf = 0.0f;  tf = ((double)b[n] >= 0.0) ? -1.0f : 1.0f;
    }
    g_thr2[n] = make_float2(mf, tf);
}

__global__ void pack_w4_kernel(const float* __restrict__ W4) {
    int t = threadIdx.x;
    if (t >= 10 * KW) return;
    int c = t >> 5, j = t & 31;
    const float4* p = reinterpret_cast<const float4*>(W4 + (size_t)c * 1024 + j * 32);
    unsigned bits = 0;
#pragma unroll
    for (int i = 0; i < 8; i++) {
        float4 v = p[i];
        bits |= (v.x >= 0.0f ? 1u : 0u) << (4 * i + 0);
        bits |= (v.y >= 0.0f ? 1u : 0u) << (4 * i + 1);
        bits |= (v.z >= 0.0f ? 1u : 0u) << (4 * i + 2);
        bits |= (v.w >= 0.0f ? 1u : 0u) << (4 * i + 3);
    }
    g_w4[c * KW + j] = bits;
}

// ======================= popc layers (L1, L3) =======================
// out_mode 0: ballot->bit word into g_act[dst]; 1: bf16 +-1 into g_abf.
__global__ void __launch_bounds__(THREADS)
layer_pop(int src, int dst, int widx, int out_mode,
          const float* __restrict__ gg, const float* __restrict__ bb,
          const float* __restrict__ mm, const float* __restrict__ vv) {
    __shared__ uint4 sh_a[ROWS_PB][8];

    const int tid  = threadIdx.x;
    const int lane = tid & 31;
    const int wid  = tid >> 5;
    const int row0 = blockIdx.x * ROWS_PB;
    const int grp  = blockIdx.y * GRP_PB + wid;
    const int n    = grp * 32 + lane;

    {
        const uint4* asrc = reinterpret_cast<const uint4*>(&g_act[src][(size_t)row0 * KW]);
        uint4* adst = &sh_a[0][0];
        for (int i = tid; i < ROWS_PB * 8; i += THREADS) adst[i] = asrc[i];
    }

    unsigned w[KW];
    const unsigned* wt = &g_wt[widx][0];
#pragma unroll
    for (int j = 0; j < KW; j++) w[j] = wt[j * HN + n];

    int thr; unsigned neg;
    {
        double gd = (double)gg[n], vd = (double)vv[n];
        double md = (double)mm[n], bd = (double)bb[n];
        double sc = gd / sqrt(vd + 1e-5);
        if (sc > 0.0) {
            double T = (1024.0 - md + bd / sc) * 0.5;
            T = fmin(fmax(T, -2.0e9), 2.0e9);
            thr = (int)floor(T); neg = 0u;
        } else if (sc < 0.0) {
            double T = (1024.0 - md + bd / sc) * 0.5;
            T = fmin(fmax(T, -2.0e9), 2.0e9);
            thr = (int)ceil(T) - 1; neg = 1u;
        } else {
            thr = (bd >= 0.0) ? 0x7fffffff : (-0x7fffffff - 1); neg = 0u;
        }
    }
    __syncthreads();

    unsigned* outb = &g_act[dst][0];
    unsigned short* outh = &g_abf[0];
#pragma unroll 2
    for (int r = 0; r < ROWS_PB; ++r) {
        unsigned x[32];
#pragma unroll
        for (int i = 0; i < 8; i++) {
            uint4 av = sh_a[r][i];
            x[4 * i + 0] = av.x ^ w[4 * i + 0];
            x[4 * i + 1] = av.y ^ w[4 * i + 1];
            x[4 * i + 2] = av.z ^ w[4 * i + 2];
            x[4 * i + 3] = av.w ^ w[4 * i + 3];
        }

        // naive POPC on x[0..8]
        int a0 = __popc(x[0]) + __popc(x[1]) + __popc(x[2]);
        int a1 = __popc(x[3]) + __popc(x[4]) + __popc(x[5]);
        int a2 = __popc(x[6]) + __popc(x[7]) + __popc(x[8]);

        // balanced CSA on x[9..31]: 16 FAs, 7 final popcs (q = 16 total)
        unsigned s0,c0,s1,c1,s2,c2,s3,c3,s4,c4,s5,c5,s6,c6;
        FA(x[9],  x[10], x[11], s0, c0);
        FA(x[12], x[13], x[14], s1, c1);
        FA(x[15], x[16], x[17], s2, c2);
        FA(x[18], x[19], x[20], s3, c3);
        FA(x[21], x[22], x[23], s4, c4);
        FA(x[24], x[25], x[26], s5, c5);
        FA(x[27], x[28], x[29], s6, c6);
        unsigned u0,d0,u1,d1,u2,d2,u3,d3;
        FA(s0, s1, s2,     u0, d0);
        FA(s3, s4, s5,     u1, d1);
        FA(s6, x[30], x[31], u2, d2);
        FA(u0, u1, u2,     u3, d3);           // w1 final: u3
        unsigned e0,f0,e1,f1,e2,f2,e3,f3,e4,f4;
        FA(c0, c1, c2, e0, f0);
        FA(c3, c4, c5, e1, f1);
        FA(c6, d0, d1, e2, f2);
        FA(e0, e1, e2, e3, f3);
        FA(e3, d2, d3, e4, f4);               // w2 final: e4; w4 finals f0..f4

        int F = (__popc(f0) + __popc(f1) + __popc(f2)) + (__popc(f3) + __popc(f4));
        int P = (a0 + a1 + a2) + __popc(u3) + 2 * __popc(e4) + 4 * F;

        unsigned bit = ((P <= thr) ? 1u : 0u) ^ neg;
        if (out_mode) {
            outh[(size_t)(row0 + r) * HN + n] = bit ? (unsigned short)0x3F80
                                                    : (unsigned short)0xBF80;
        } else {
            unsigned wordbits = __ballot_sync(0xffffffffu, bit != 0u);
            if (lane == 0) outb[(size_t)(row0 + r) * KW + grp] = wordbits;
        }
    }
}

// ======================= L2: bf16 mma.sync GEMM =======================
// grid (128, 8), 256 thr. CTA tile 128x128, BK=64, cp.async double buffer,
// ldmatrix fragments, f32 accum (exact), threshold epilogue -> packed bits.
#define L2_SMEM (65536 + 1024)

__global__ void __launch_bounds__(256)
gemm_l2(unsigned* __restrict__ outbits) {
    extern __shared__ unsigned char ds[];
    const int tid = threadIdx.x, lane = tid & 31, wid = tid >> 5;
    const int m0 = blockIdx.x * 128, n0 = blockIdx.y * 128;
    const int wm = (wid & 3) * 32, wn = (wid >> 2) * 64;
    const unsigned short* A = &g_abf[0];
    const unsigned short* B = &g_wbf[0];

    float2* sthr = reinterpret_cast<float2*>(ds + 65536);
    if (tid < 128) sthr[tid] = g_thr2[n0 + tid];

    float acc[2][8][4];
#pragma unroll
    for (int a = 0; a < 2; a++)
#pragma unroll
        for (int b = 0; b < 8; b++)
#pragma unroll
            for (int c = 0; c < 4; c++) acc[a][b][c] = 0.0f;

    auto stage = [&](int kc) {
        int buf = kc & 1;
        const unsigned short* ga = A + (size_t)m0 * 1024 + kc * 64;
        const unsigned short* gb = B + (size_t)n0 * 1024 + kc * 64;
        unsigned char* Ab = ds + buf * 16384;
        unsigned char* Bb = ds + 32768 + buf * 16384;
#pragma unroll
        for (int t = 0; t < 4; t++) {
            int i = tid + t * 256;
            int r = i >> 3, c16 = i & 7;
            uint32_t da = smem_u32(Ab + r * 128 + ((c16 ^ (r & 7)) << 4));
            asm volatile("cp.async.cg.shared.global [%0], [%1], 16;"
                         :: "r"(da), "l"(ga + (size_t)r * 1024 + c16 * 8) : "memory");
        }
#pragma unroll
        for (int t = 0; t < 4; t++) {
            int i = tid + t * 256;
            int r = i >> 3, c16 = i & 7;
            uint32_t db = smem_u32(Bb + r * 128 + ((c16 ^ (r & 7)) << 4));
            asm volatile("cp.async.cg.shared.global [%0], [%1], 16;"
                         :: "r"(db), "l"(gb + (size_t)r * 1024 + c16 * 8) : "memory");
        }
        asm volatile("cp.async.commit_group;" ::: "memory");
    };

    stage(0);
    const int rsel = lane & 15, csel = lane >> 4;
    for (int kc = 0; kc < 16; kc++) {
        if (kc < 15) {
            stage(kc + 1);
            asm volatile("cp.async.wait_group 1;" ::: "memory");
        } else {
            asm volatile("cp.async.wait_group 0;" ::: "memory");
        }
        __syncthreads();

        const unsigned char* Ab = ds + (kc & 1) * 16384;
        const unsigned char* Bb = ds + 32768 + (kc & 1) * 16384;
#pragma unroll
        for (int kt = 0; kt < 4; kt++) {
            unsigned afr[2][4];
#pragma unroll
            for (int mt = 0; mt < 2; mt++) {
                int row = wm + mt * 16 + rsel;
                int c16 = kt * 2 + csel;
                uint32_t ad = smem_u32(Ab + row * 128 + ((c16 ^ (row & 7)) << 4));
                asm volatile("ldmatrix.sync.aligned.m8n8.x4.shared.b16 {%0,%1,%2,%3}, [%4];"
                             : "=r"(afr[mt][0]), "=r"(afr[mt][1]),
                               "=r"(afr[mt][2]), "=r"(afr[mt][3]) : "r"(ad));
            }
            unsigned bfr[4][4];
#pragma unroll
            for (int np = 0; np < 4; np++) {
                int row = wn + np * 16 + rsel;
                int c16 = kt * 2 + csel;
                uint32_t bd = smem_u32(Bb + row * 128 + ((c16 ^ (row & 7)) << 4));
                asm volatile("ldmatrix.sync.aligned.m8n8.x4.shared.b16 {%0,%1,%2,%3}, [%4];"
                             : "=r"(bfr[np][0]), "=r"(bfr[np][1]),
                               "=r"(bfr[np][2]), "=r"(bfr[np][3]) : "r"(bd));
            }
#pragma unroll
            for (int nt = 0; nt < 8; nt++) {
                unsigned b0 = bfr[nt >> 1][(nt & 1) ? 1 : 0];
                unsigned b1 = bfr[nt >> 1][(nt & 1) ? 3 : 2];
#pragma unroll
                for (int mt = 0; mt < 2; mt++) {
                    asm volatile(
                        "mma.sync.aligned.m16n8k16.row.col.f32.bf16.bf16.f32 "
                        "{%0,%1,%2,%3}, {%4,%5,%6,%7}, {%8,%9}, {%0,%1,%2,%3};"
                        : "+f"(acc[mt][nt][0]), "+f"(acc[mt][nt][1]),
                          "+f"(acc[mt][nt][2]), "+f"(acc[mt][nt][3])
                        : "r"(afr[mt][0]), "r"(afr[mt][1]),
                          "r"(afr[mt][2]), "r"(afr[mt][3]), "r"(b0), "r"(b1));
                }
            }
        }
        __syncthreads();
    }

    // epilogue: threshold -> 0/1 bytes in smem, then pack to bit words
    unsigned char* Ob = ds;   // 16KB [128][128]
#pragma unroll
    for (int mt = 0; mt < 2; mt++) {
        int r = wm + mt * 16 + (lane >> 2);
#pragma unroll
        for (int nt = 0; nt < 8; nt++) {
            int c = wn + nt * 8 + (lane & 3) * 2;
            float2 t0 = sthr[c], t1 = sthr[c + 1];
            unsigned b00 = (fmaf(acc[mt][nt][0], t0.x, -t0.y) >= 0.0f) ? 1u : 0u;
            unsigned b01 = (fmaf(acc[mt][nt][1], t1.x, -t1.y) >= 0.0f) ? 1u : 0u;
            unsigned b10 = (fmaf(acc[mt][nt][2], t0.x, -t0.y) >= 0.0f) ? 1u : 0u;
            unsigned b11 = (fmaf(acc[mt][nt][3], t1.x, -t1.y) >= 0.0f) ? 1u : 0u;
            *(unsigned short*)(Ob + r * 128 + c)       = (unsigned short)(b00 | (b01 << 8));
            *(unsigned short*)(Ob + (r + 8) * 128 + c) = (unsigned short)(b10 | (b11 << 8));
        }
    }
    __syncthreads();
#pragma unroll
    for (int t = 0; t < 2; t++) {
        int wi = tid * 2 + t;                 // 0..511
        int r = wi >> 2, g = wi & 3;
        const unsigned* p = reinterpret_cast<const unsigned*>(Ob + r * 128 + g * 32);
        unsigned word = 0;
#pragma unroll
        for (int i = 0; i < 8; i++) {
            unsigned v = p[i] & 0x01010101u;
            unsigned nib = (v * 0x01020408u) >> 24;    // 4 bits, exact
            word |= nib << (i * 4);
        }
        outbits[(size_t)(m0 + r) * KW + (n0 >> 5) + g] = word;
    }
}

// ======================= final layer + TensorNorm =======================
__global__ void final_kernel(const float* __restrict__ tnw, const float* __restrict__ tnb,
                             const float* __restrict__ tnm, const float* __restrict__ tnv,
                             float* __restrict__ out) {
    __shared__ unsigned sw[10 * KW];
    const int tid = threadIdx.x;
    for (int i = tid; i < 10 * KW; i += blockDim.x) sw[i] = g_w4[i];
    __syncthreads();

    int row = blockIdx.x * blockDim.x + tid;
    if (row >= NB) return;

    uint4 a[8];
    const uint4* p = reinterpret_cast<const uint4*>(&g_act[1][(size_t)row * KW]);
#pragma unroll
    for (int i = 0; i < 8; i++) a[i] = p[i];

    float rs = (float)(1.0 / sqrt((double)tnv[0] + 1e-4));
    float wq = tnw[0], bq = tnb[0], mq = tnm[0];

#pragma unroll
    for (int c = 0; c < 10; c++) {
        int P = 0;
#pragma unroll
        for (int i = 0; i < 8; i++) {
            P += __popc(a[i].x ^ sw[c * KW + 4 * i + 0]);
            P += __popc(a[i].y ^ sw[c * KW + 4 * i + 1]);
            P += __popc(a[i].z ^ sw[c * KW + 4 * i + 2]);
            P += __popc(a[i].w ^ sw[c * KW + 4 * i + 3]);
        }
        float s = (float)(1024 - 2 * P);
        out[(size_t)row * 10 + c] = ((s - mq) * rs) * wq + bq;
    }
}

// ======================= launch =======================
extern "C" void kernel_launch(void* const* d_in, const int* in_sizes, int n_in,
                              void* d_out, int out_size) {
    const float* x  = (const float*)d_in[0];
    const float* W1 = (const float*)d_in[1];
    const float* W2 = (const float*)d_in[2];
    const float* W3 = (const float*)d_in[3];
    const float* W4 = (const float*)d_in[4];
    const float* g1 = (const float*)d_in[5],  *b1 = (const float*)d_in[6];
    const float* m1 = (const float*)d_in[7],  *v1 = (const float*)d_in[8];
    const float* g2 = (const float*)d_in[9],  *b2 = (const float*)d_in[10];
    const float* m2 = (const float*)d_in[11], *v2 = (const float*)d_in[12];
    const float* g3 = (const float*)d_in[13], *b3 = (const float*)d_in[14];
    const float* m3 = (const float*)d_in[15], *v3 = (const float*)d_in[16];
    const float* tnw = (const float*)d_in[17], *tnb = (const float*)d_in[18];
    const float* tnm = (const float*)d_in[19], *tnv = (const float*)d_in[20];
    float* out = (float*)d_out;

    cudaFuncSetAttribute(gemm_l2, cudaFuncAttributeMaxDynamicSharedMemorySize, L2_SMEM);

    void* pb;
    cudaGetSymbolAddress(&pb, g_act);
    unsigned* act0 = (unsigned*)pb;                  // g_act[0]

    pack_x_kernel<<<(NB * KW + 255) / 256, 256>>>(x);
    pack_w_kernel<<<(KW * HN + 255) / 256, 256>>>(W1, 0);
    pack_w_kernel<<<(KW * HN + 255) / 256, 256>>>(W3, 1);
    conv_w2<<<HN * HN / 4 / 256, 256>>>(W2);
    thr2_kernel<<<4, 256>>>(g2, b2, m2, v2);
    pack_w4_kernel<<<1, 320>>>(W4);

    dim3 lgrid(NB / ROWS_PB, HN / (GRP_PB * 32));    // (128, 4)
    // L1: bits -> bf16
    layer_pop<<<lgrid, THREADS>>>(0, 0, 0, 1, g1, b1, m1, v1);
    // L2: bf16 GEMM -> bits into g_act[0]
    dim3 ggrid(NB / 128, HN / 128);                  // (128, 8)
    gemm_l2<<<ggrid, 256, L2_SMEM>>>(act0);
    // L3: bits -> bits into g_act[1]
    layer_pop<<<lgrid, THREADS>>>(0, 1, 1, 0, g3, b3, m3, v3);

    final_kernel<<<NB / 256, 256>>>(tnw, tnb, tnm, tnv, out);
}

// round 9
// speedup vs baseline: 1.2492x; 1.2492x over previous
#include <cuda_runtime.h>
#include <cstdint>
#include <math.h>

// Binary MLP B=16384, D=H=1024, C=10 — all-popc path.
// Bit-packed XOR + balanced CSA(q=16) bit-count; BN+sign folded to an integer
// threshold (precomputed exactly in double); 2 rows/iteration for ILP.

#define NB       16384
#define KW       32
#define HN       1024
#define ROWS_PB  64
#define GRP_PB   8
#define THREADS  256

__device__ unsigned g_act[2][NB * KW];     // ping-pong packed activations
__device__ unsigned g_wt[3][KW * HN];      // packed hidden weights [word j][neuron n]
__device__ unsigned g_w4[10 * KW];         // packed output weights
__device__ int2     g_thri[3 * HN];        // (thr, neg) per neuron per layer

__device__ __forceinline__ unsigned lop3_96(unsigned a, unsigned b, unsigned c) { // a^b^c
    unsigned r;
    asm("lop3.b32 %0, %1, %2, %3, 0x96;" : "=r"(r) : "r"(a), "r"(b), "r"(c));
    return r;
}
__device__ __forceinline__ unsigned lop3_e8(unsigned a, unsigned b, unsigned c) { // maj
    unsigned r;
    asm("lop3.b32 %0, %1, %2, %3, 0xE8;" : "=r"(r) : "r"(a), "r"(b), "r"(c));
    return r;
}
#define FA(a, b, c, s, cy) { s = lop3_96(a, b, c); cy = lop3_e8(a, b, c); }

// exact 1024-bit popcount of x[0..31]: 9 naive + 23-word CSA (16 FAs, 7 popcs)
__device__ __forceinline__ int count1024(const unsigned* __restrict__ x) {
    int a0 = __popc(x[0]) + __popc(x[1]) + __popc(x[2]);
    int a1 = __popc(x[3]) + __popc(x[4]) + __popc(x[5]);
    int a2 = __popc(x[6]) + __popc(x[7]) + __popc(x[8]);

    unsigned s0,c0,s1,c1,s2,c2,s3,c3,s4,c4,s5,c5,s6,c6;
    FA(x[9],  x[10], x[11], s0, c0);
    FA(x[12], x[13], x[14], s1, c1);
    FA(x[15], x[16], x[17], s2, c2);
    FA(x[18], x[19], x[20], s3, c3);
    FA(x[21], x[22], x[23], s4, c4);
    FA(x[24], x[25], x[26], s5, c5);
    FA(x[27], x[28], x[29], s6, c6);
    unsigned u0,d0,u1,d1,u2,d2,u3,d3;
    FA(s0, s1, s2,       u0, d0);
    FA(s3, s4, s5,       u1, d1);
    FA(s6, x[30], x[31], u2, d2);
    FA(u0, u1, u2,       u3, d3);
    unsigned e0,f0,e1,f1,e2,f2,e3,f3,e4,f4;
    FA(c0, c1, c2, e0, f0);
    FA(c3, c4, c5, e1, f1);
    FA(c6, d0, d1, e2, f2);
    FA(e0, e1, e2, e3, f3);
    FA(e3, d2, d3, e4, f4);

    int F = (__popc(f0) + __popc(f1) + __popc(f2)) + (__popc(f3) + __popc(f4));
    return (a0 + a1 + a2) + __popc(u3) + 2 * __popc(e4) + 4 * F;
}

// ======================= prep kernels =======================
__global__ void pack_x_kernel(const float* __restrict__ x) {
    int t = blockIdx.x * blockDim.x + threadIdx.x;
    if (t >= NB * KW) return;
    int row = t >> 5, w = t & 31;
    const float4* p = reinterpret_cast<const float4*>(x + (size_t)row * 1024 + w * 32);
    unsigned bits = 0;
#pragma unroll
    for (int i = 0; i < 8; i++) {
        float4 v = p[i];
        bits |= ((2.0f * v.x - 1.0f) >= 0.0f ? 1u : 0u) << (4 * i + 0);
        bits |= ((2.0f * v.y - 1.0f) >= 0.0f ? 1u : 0u) << (4 * i + 1);
        bits |= ((2.0f * v.z - 1.0f) >= 0.0f ? 1u : 0u) << (4 * i + 2);
        bits |= ((2.0f * v.w - 1.0f) >= 0.0f ? 1u : 0u) << (4 * i + 3);
    }
    g_act[0][t] = bits;
}

__global__ void pack_w_kernel(const float* __restrict__ W, int widx) {
    int t = blockIdx.x * blockDim.x + threadIdx.x;
    if (t >= KW * HN) return;
    int n = t & (HN - 1), j = t >> 10;
    const float4* p = reinterpret_cast<const float4*>(W + (size_t)n * 1024 + j * 32);
    unsigned bits = 0;
#pragma unroll
    for (int i = 0; i < 8; i++) {
        float4 v = p[i];
        bits |= (v.x >= 0.0f ? 1u : 0u) << (4 * i + 0);
        bits |= (v.y >= 0.0f ? 1u : 0u) << (4 * i + 1);
        bits |= (v.z >= 0.0f ? 1u : 0u) << (4 * i + 2);
        bits |= (v.w >= 0.0f ? 1u : 0u) << (4 * i + 3);
    }
    g_wt[widx][j * HN + n] = bits;
}

__global__ void pack_w4_kernel(const float* __restrict__ W4) {
    int t = threadIdx.x;
    if (t >= 10 * KW) return;
    int c = t >> 5, j = t & 31;
    const float4* p = reinterpret_cast<const float4*>(W4 + (size_t)c * 1024 + j * 32);
    unsigned bits = 0;
#pragma unroll
    for (int i = 0; i < 8; i++) {
        float4 v = p[i];
        bits |= (v.x >= 0.0f ? 1u : 0u) << (4 * i + 0);
        bits |= (v.y >= 0.0f ? 1u : 0u) << (4 * i + 1);
        bits |= (v.z >= 0.0f ? 1u : 0u) << (4 * i + 2);
        bits |= (v.w >= 0.0f ? 1u : 0u) << (4 * i + 3);
    }
    g_w4[c * KW + j] = bits;
}

// exact integer thresholds: bit = ((P <= thr) ? 1 : 0) ^ neg
__global__ void thr_kernel(const float* __restrict__ g, const float* __restrict__ b,
                           const float* __restrict__ m, const float* __restrict__ v,
                           int2* __restrict__ out) {
    int n = blockIdx.x * blockDim.x + threadIdx.x;
    if (n >= HN) return;
    double sc = (double)g[n] / sqrt((double)v[n] + 1e-5);
    int thr; int neg;
    if (sc > 0.0) {
        double T = (1024.0 - (double)m[n] + (double)b[n] / sc) * 0.5;
        T = fmin(fmax(T, -2.0e9), 2.0e9);
        thr = (int)floor(T); neg = 0;
    } else if (sc < 0.0) {
        double T = (1024.0 - (double)m[n] + (double)b[n] / sc) * 0.5;
        T = fmin(fmax(T, -2.0e9), 2.0e9);
        thr = (int)ceil(T) - 1; neg = 1;
    } else {
        thr = ((double)b[n] >= 0.0) ? 0x7fffffff : (-0x7fffffff - 1); neg = 0;
    }
    out[n] = make_int2(thr, neg);
}

// ======================= hidden layer =======================
// grid (NB/ROWS_PB, HN/256) = (256, 4); 8 warps, one 32-neuron group each;
// 2 rows per inner iteration for ILP.
__global__ void __launch_bounds__(THREADS)
layer_kernel(int src, int dst, int widx, const int2* __restrict__ thrv) {
    __shared__ uint4 sh_a[ROWS_PB][8];

    const int tid  = threadIdx.x;
    const int lane = tid & 31;
    const int wid  = tid >> 5;
    const int row0 = blockIdx.x * ROWS_PB;
    const int grp  = blockIdx.y * GRP_PB + wid;
    const int n    = grp * 32 + lane;

    {   // stage A tile: 64 rows x 32 words = 512 uint4
        const uint4* asrc = reinterpret_cast<const uint4*>(&g_act[src][(size_t)row0 * KW]);
        uint4* adst = &sh_a[0][0];
#pragma unroll
        for (int t = 0; t < ROWS_PB * 8 / THREADS; t++)
            adst[tid + t * THREADS] = asrc[tid + t * THREADS];
    }

    unsigned w[KW];
    const unsigned* wt = &g_wt[widx][0];
#pragma unroll
    for (int j = 0; j < KW; j++) w[j] = wt[j * HN + n];

    const int2 tn  = thrv[n];
    const int  thr = tn.x;
    const unsigned neg = (unsigned)tn.y;
    __syncthreads();

    unsigned* out = &g_act[dst][0];
    for (int r = 0; r < ROWS_PB; r += 2) {
        unsigned x0[32], x1[32];
#pragma unroll
        for (int i = 0; i < 8; i++) {
            uint4 a0 = sh_a[r][i];
            uint4 a1 = sh_a[r + 1][i];
            x0[4 * i + 0] = a0.x ^ w[4 * i + 0];
            x0[4 * i + 1] = a0.y ^ w[4 * i + 1];
            x0[4 * i + 2] = a0.z ^ w[4 * i + 2];
            x0[4 * i + 3] = a0.w ^ w[4 * i + 3];
            x1[4 * i + 0] = a1.x ^ w[4 * i + 0];
            x1[4 * i + 1] = a1.y ^ w[4 * i + 1];
            x1[4 * i + 2] = a1.z ^ w[4 * i + 2];
            x1[4 * i + 3] = a1.w ^ w[4 * i + 3];
        }
        int P0 = count1024(x0);
        int P1 = count1024(x1);

        unsigned bit0 = ((P0 <= thr) ? 1u : 0u) ^ neg;
        unsigned bit1 = ((P1 <= thr) ? 1u : 0u) ^ neg;
        unsigned wb0 = __ballot_sync(0xffffffffu, bit0 != 0u);
        unsigned wb1 = __ballot_sync(0xffffffffu, bit1 != 0u);
        if (lane == 0) {
            out[(size_t)(row0 + r)     * KW + grp] = wb0;
            out[(size_t)(row0 + r + 1) * KW + grp] = wb1;
        }
    }
}

// ======================= final layer + TensorNorm =======================
__global__ void final_kernel(const float* __restrict__ tnw, const float* __restrict__ tnb,
                             const float* __restrict__ tnm, const float* __restrict__ tnv,
                             float* __restrict__ out) {
    __shared__ unsigned sw[10 * KW];
    const int tid = threadIdx.x;
    for (int i = tid; i < 10 * KW; i += blockDim.x) sw[i] = g_w4[i];
    __syncthreads();

    int row = blockIdx.x * blockDim.x + tid;
    if (row >= NB) return;

    uint4 a[8];
    const uint4* p = reinterpret_cast<const uint4*>(&g_act[1][(size_t)row * KW]);
#pragma unroll
    for (int i = 0; i < 8; i++) a[i] = p[i];

    float rs = (float)(1.0 / sqrt((double)tnv[0] + 1e-4));
    float wq = tnw[0], bq = tnb[0], mq = tnm[0];

#pragma unroll
    for (int c = 0; c < 10; c++) {
        int P = 0;
#pragma unroll
        for (int i = 0; i < 8; i++) {
            P += __popc(a[i].x ^ sw[c * KW + 4 * i + 0]);
            P += __popc(a[i].y ^ sw[c * KW + 4 * i + 1]);
            P += __popc(a[i].z ^ sw[c * KW + 4 * i + 2]);
            P += __popc(a[i].w ^ sw[c * KW + 4 * i + 3]);
        }
        float s = (float)(1024 - 2 * P);
        out[(size_t)row * 10 + c] = ((s - mq) * rs) * wq + bq;
    }
}

// ======================= launch =======================
extern "C" void kernel_launch(void* const* d_in, const int* in_sizes, int n_in,
                              void* d_out, int out_size) {
    const float* x  = (const float*)d_in[0];
    const float* W1 = (const float*)d_in[1];
    const float* W2 = (const float*)d_in[2];
    const float* W3 = (const float*)d_in[3];
    const float* W4 = (const float*)d_in[4];
    const float* g1 = (const float*)d_in[5],  *b1 = (const float*)d_in[6];
    const float* m1 = (const float*)d_in[7],  *v1 = (const float*)d_in[8];
    const float* g2 = (const float*)d_in[9],  *b2 = (const float*)d_in[10];
    const float* m2 = (const float*)d_in[11], *v2 = (const float*)d_in[12];
    const float* g3 = (const float*)d_in[13], *b3 = (const float*)d_in[14];
    const float* m3 = (const float*)d_in[15], *v3 = (const float*)d_in[16];
    const float* tnw = (const float*)d_in[17], *tnb = (const float*)d_in[18];
    const float* tnm = (const float*)d_in[19], *tnv = (const float*)d_in[20];
    float* out = (float*)d_out;

    void* pt;
    cudaGetSymbolAddress(&pt, g_thri);
    int2* tv = (int2*)pt;

    pack_x_kernel<<<(NB * KW + 255) / 256, 256>>>(x);
    pack_w_kernel<<<(KW * HN + 255) / 256, 256>>>(W1, 0);
    pack_w_kernel<<<(KW * HN + 255) / 256, 256>>>(W2, 1);
    pack_w_kernel<<<(KW * HN + 255) / 256, 256>>>(W3, 2);
    thr_kernel<<<4, 256>>>(g1, b1, m1, v1, tv);
    thr_kernel<<<4, 256>>>(g2, b2, m2, v2, tv + 1024);
    thr_kernel<<<4, 256>>>(g3, b3, m3, v3, tv + 2048);
    pack_w4_kernel<<<1, 320>>>(W4);

    dim3 lgrid(NB / ROWS_PB, HN / (GRP_PB * 32));    // (256, 4)
    layer_kernel<<<lgrid, THREADS>>>(0, 1, 0, tv);
    layer_kernel<<<lgrid, THREADS>>>(1, 0, 1, tv + 1024);
    layer_kernel<<<lgrid, THREADS>>>(0, 1, 2, tv + 2048);

    final_kernel<<<NB / 256, 256>>>(tnw, tnb, tnm, tnv, out);
}